// round 8
// baseline (speedup 1.0000x reference)
#include <cuda_runtime.h>
#include <math.h>

#define NW 1e-5f
#define CUTOFF_F 3.0f
#define SQRT2_F 1.41421356237309515f
#define INV_SQRT_PI_F 0.5641895835477563f
#define SQRT_LOG2E 1.2011224087864498f      // sqrt(log2(e))
#define NEG_LIM (-12.98325536919584f)       // -9 * log2(e)

#define TPB 256
#define NPT 2
#define NTILE (TPB * NPT)      // 512 n-points per block
#define CHUNK 128              // m-values per block
#define NWARPS (TPB / 32)

__global__ void zero_out_kernel(float* __restrict__ out, int BN) {
    int i = blockIdx.x * blockDim.x + threadIdx.x;
    if (i < BN) out[i] = 0.0f;
}

__global__ void __launch_bounds__(TPB)
spectra_main_kernel(const float* __restrict__ res_fields,
                    const float* __restrict__ width,
                    const float* __restrict__ A_mean,
                    const float* __restrict__ area,
                    const float* __restrict__ sf,
                    float* __restrict__ out,
                    int B, int M, int N) {
    __shared__ float4 sp[CHUNK];          // compacted params: {mu*c*s, c*s, k/s, pad}
    __shared__ int   s_warpcnt[NWARPS];
    __shared__ float s_flo, s_fhi;

    const int b  = blockIdx.z;
    const int mc = blockIdx.y;            // m-chunk index
    const int n_base = blockIdx.x * NTILE;
    const int n0 = n_base + threadIdx.x;
    const int n1 = n0 + TPB;
    const int lane = threadIdx.x & 31;
    const int wid  = threadIdx.x >> 5;

    // Block's field range (for window-intersection culling)
    if (threadIdx.x == 0) {
        int nhi = n_base + NTILE - 1; if (nhi >= N) nhi = N - 1;
        s_flo = sf[b * N + n_base];
        s_fhi = sf[b * N + nhi];
    }

    // Per-thread field values (clamped loads; guarded output at end)
    const int n0c = (n0 < N) ? n0 : (N - 1);
    const int n1c = (n1 < N) ? n1 : (N - 1);
    const float fn0 = -sf[b * N + n0c];
    const float fn1 = -sf[b * N + n1c];
    // exact half grid spacing for this batch
    const float sw = (sf[b * N + 1] - sf[b * N]) * 0.5f;

    __syncthreads();
    const float bc = 0.5f * (s_flo + s_fhi);
    const float hr = 0.5f * (s_fhi - s_flo);

    // ---- Fused param computation for m = mc*CHUNK + threadIdx.x (first CHUNK threads) ----
    const int mi = threadIdx.x;
    const int m = mc * CHUNK + mi;
    bool keep = false;
    float4 prm;
    if (mi < CHUNK && m < M) {
        const int idx = b * M + m;
        float r0 = res_fields[idx * 3 + 0];
        float r1 = res_fields[idx * 3 + 1];
        float r2 = res_fields[idx * 3 + 2];
        float t;
        if (r0 < r1) { t = r0; r0 = r1; r1 = t; }
        if (r1 < r2) { t = r1; r1 = r2; r2 = t; }
        if (r0 < r1) { t = r0; r0 = r1; r1 = t; }

        float w = width[idx];
        w = (w > NW) ? w : w + NW;
        float invw = __fdividef(1.0f, w);
        float d13 = (r0 - r2) * invw;
        float d23 = (r1 - r2) * invw;
        float d12 = (r0 - r1) * invw;
        float add = (d13 * d13 + d23 * d23 + d12 * d12) * (1.0f / 9.0f);
        w = (w > 2.0f * NW) ? w : w + 2.0f * NW;

        float ew = sqrtf(w * w * (1.0f + add) + sw * sw);
        ew = (ew < sw * 0.5f) ? ew : ew + sw * 0.5f;

        float mu = (r0 + r1 + r2) * (1.0f / 3.0f);
        float c  = SQRT2_F / ew;
        float A  = A_mean[idx] * area[m];
        float k  = 2.0f * A * c * c * INV_SQRT_PI_F;

        // Window-intersection test against block n-range
        float d = fabsf(mu - bc) - hr;
        if (d < 0.0f) d = 0.0f;
        keep = (d * c <= CUTOFF_F);

        // log2-domain params
        prm = make_float4(mu * c * SQRT_LOG2E, c * SQRT_LOG2E, k / SQRT_LOG2E, 0.0f);
    }

    // ---- Order-preserving compaction into shared ----
    unsigned bal = __ballot_sync(0xffffffffu, keep);
    if (lane == 0) s_warpcnt[wid] = __popc(bal);
    __syncthreads();

    int offset = __popc(bal & ((1u << lane) - 1u));
    int total = 0;
#pragma unroll
    for (int wi = 0; wi < NWARPS; ++wi) {
        int cnt = s_warpcnt[wi];
        if (wi < wid) offset += cnt;
        total += cnt;
    }
    if (keep) sp[offset] = prm;
    __syncthreads();

    // ---- Main accumulation: 2 n-points per thread, fully predicated ----
    float acc0 = 0.0f, acc1 = 0.0f;
    const float lim = NEG_LIM;
#pragma unroll 4
    for (int j = 0; j < total; ++j) {
        float4 p = sp[j];                            // broadcast LDS.128

        float argl0 = fmaf(fn0, p.y, p.x);
        float argl1 = fmaf(fn1, p.y, p.x);
        float tneg0 = argl0 * (-argl0);
        float tneg1 = argl1 * (-argl1);
        float e0, e1;
        asm("ex2.approx.ftz.f32 %0, %1;" : "=f"(e0) : "f"(tneg0));
        asm("ex2.approx.ftz.f32 %0, %1;" : "=f"(e1) : "f"(tneg1));
        float g0 = argl0 * e0;
        float g1 = argl1 * e1;
        asm("{\n\t"
            ".reg .pred q;\n\t"
            "setp.ge.f32 q, %1, %2;\n\t"
            "@q fma.rn.f32 %0, %3, %4, %0;\n\t"
            "}"
            : "+f"(acc0)
            : "f"(tneg0), "f"(lim), "f"(g0), "f"(p.z));
        asm("{\n\t"
            ".reg .pred q;\n\t"
            "setp.ge.f32 q, %1, %2;\n\t"
            "@q fma.rn.f32 %0, %3, %4, %0;\n\t"
            "}"
            : "+f"(acc1)
            : "f"(tneg1), "f"(lim), "f"(g1), "f"(p.z));
    }

    if (n0 < N) atomicAdd(&out[b * N + n0], acc0);
    if (n1 < N) atomicAdd(&out[b * N + n1], acc1);
}

extern "C" void kernel_launch(void* const* d_in, const int* in_sizes, int n_in,
                              void* d_out, int out_size) {
    const float* res_fields = (const float*)d_in[0];   // [B, M, 3]
    const float* width      = (const float*)d_in[1];   // [B, M]
    const float* A_mean     = (const float*)d_in[2];   // [B, M]
    const float* area       = (const float*)d_in[3];   // [M]
    const float* sf         = (const float*)d_in[4];   // [B, N]
    float* out = (float*)d_out;                        // [B, N]

    int M = in_sizes[3];
    int B = in_sizes[1] / M;
    int N = in_sizes[4] / B;

    int BN = B * N;
    int num_chunks = (M + CHUNK - 1) / CHUNK;
    int nblocks = (N + NTILE - 1) / NTILE;

    zero_out_kernel<<<(BN + TPB - 1) / TPB, TPB>>>(out, BN);

    dim3 grid(nblocks, num_chunks, B);
    spectra_main_kernel<<<grid, TPB>>>(res_fields, width, A_mean, area, sf, out, B, M, N);
}

// round 9
// speedup vs baseline: 1.1098x; 1.1098x over previous
#include <cuda_runtime.h>
#include <math.h>

#define NW 1e-5f
#define CUTOFF_F 3.0f
#define SQRT2_F 1.41421356237309515f
#define INV_SQRT_PI_F 0.5641895835477563f
#define SQRT_LOG2E 1.2011224087864498f      // sqrt(log2(e))
#define NEG_LIM (-12.98325536919584f)       // -9 * log2(e)

#define TPB 256
#define CHUNK 128              // m-values per block
#define NWARPS (TPB / 32)

__global__ void zero_out_kernel(float* __restrict__ out, int BN) {
    int i = blockIdx.x * blockDim.x + threadIdx.x;
    if (i < BN) out[i] = 0.0f;
}

__global__ void __launch_bounds__(TPB)
spectra_main_kernel(const float* __restrict__ res_fields,
                    const float* __restrict__ width,
                    const float* __restrict__ A_mean,
                    const float* __restrict__ area,
                    const float* __restrict__ sf,
                    float* __restrict__ out,
                    int B, int M, int N) {
    __shared__ float4 sp[CHUNK];          // compacted params: {mu*c*s, c*s, k/s, pad}
    __shared__ int   s_warpcnt[NWARPS];
    __shared__ float s_flo, s_fhi;

    const int b  = blockIdx.z;
    const int mc = blockIdx.y;            // m-chunk index

    // Center-out remap of the n-tile index: heavy (center-field) tiles get the
    // earliest bids, light edge tiles run last -> shorter imbalance tail.
    const int nb = gridDim.x;
    const int x  = blockIdx.x;
    const int half = nb >> 1;
    int xx = (x & 1) ? (half - 1 - (x >> 1)) : (half + (x >> 1));
    if (xx < 0) xx = 0;
    if (xx >= nb) xx = nb - 1;

    const int n  = xx * TPB + threadIdx.x;
    const int lane = threadIdx.x & 31;
    const int wid  = threadIdx.x >> 5;

    // Block's field range (for window-intersection culling)
    if (threadIdx.x == 0) {
        int n0 = xx * TPB;
        int n1 = n0 + TPB - 1; if (n1 >= N) n1 = N - 1;
        s_flo = sf[b * N + n0];
        s_fhi = sf[b * N + n1];
    }

    // Per-thread field value (clamped load; guarded output at end)
    const int nc = (n < N) ? n : (N - 1);
    const float f = sf[b * N + nc];
    const float fn = -f;
    // exact half grid spacing for this batch
    const float sw = (sf[b * N + 1] - sf[b * N]) * 0.5f;

    __syncthreads();
    const float bc = 0.5f * (s_flo + s_fhi);
    const float hr = 0.5f * (s_fhi - s_flo);

    // ---- Fused param computation for m = mc*CHUNK + threadIdx.x (first CHUNK threads) ----
    const int mi = threadIdx.x;
    const int m = mc * CHUNK + mi;
    bool keep = false;
    float4 prm;
    if (mi < CHUNK && m < M) {
        const int idx = b * M + m;
        float r0 = res_fields[idx * 3 + 0];
        float r1 = res_fields[idx * 3 + 1];
        float r2 = res_fields[idx * 3 + 2];
        float t;
        if (r0 < r1) { t = r0; r0 = r1; r1 = t; }
        if (r1 < r2) { t = r1; r1 = r2; r2 = t; }
        if (r0 < r1) { t = r0; r0 = r1; r1 = t; }

        float w = width[idx];
        w = (w > NW) ? w : w + NW;
        float invw = __fdividef(1.0f, w);
        float d13 = (r0 - r2) * invw;
        float d23 = (r1 - r2) * invw;
        float d12 = (r0 - r1) * invw;
        float add = (d13 * d13 + d23 * d23 + d12 * d12) * (1.0f / 9.0f);
        w = (w > 2.0f * NW) ? w : w + 2.0f * NW;

        float ew = sqrtf(w * w * (1.0f + add) + sw * sw);
        ew = (ew < sw * 0.5f) ? ew : ew + sw * 0.5f;

        float mu = (r0 + r1 + r2) * (1.0f / 3.0f);
        float c  = SQRT2_F / ew;
        float A  = A_mean[idx] * area[m];
        float k  = 2.0f * A * c * c * INV_SQRT_PI_F;

        // Window-intersection test against block n-range
        float d = fabsf(mu - bc) - hr;
        if (d < 0.0f) d = 0.0f;
        keep = (d * c <= CUTOFF_F);

        // log2-domain params
        prm = make_float4(mu * c * SQRT_LOG2E, c * SQRT_LOG2E, k / SQRT_LOG2E, 0.0f);
    }

    // ---- Order-preserving compaction into shared ----
    unsigned bal = __ballot_sync(0xffffffffu, keep);
    if (lane == 0) s_warpcnt[wid] = __popc(bal);
    __syncthreads();

    int offset = __popc(bal & ((1u << lane) - 1u));
    int total = 0;
#pragma unroll
    for (int wi = 0; wi < NWARPS; ++wi) {
        int cnt = s_warpcnt[wi];
        if (wi < wid) offset += cnt;
        total += cnt;
    }
    if (keep) sp[offset] = prm;
    __syncthreads();

    // ---- Main accumulation over surviving m's (branchless, log2-domain, predicated FMA) ----
    float acc = 0.0f;
    const float lim = NEG_LIM;
#pragma unroll 8
    for (int j = 0; j < total; ++j) {
        float4 p = sp[j];                           // broadcast LDS.128
        float argl = fmaf(fn, p.y, p.x);            // (mu - f) * c * sqrt(log2e)
        float tneg = argl * (-argl);                // -arg^2 * log2e (neg modifier free)
        float e;
        asm("ex2.approx.ftz.f32 %0, %1;" : "=f"(e) : "f"(tneg));   // MUFU.EX2
        float g = argl * e;
        // predicated accumulate: FSETP + @P FFMA (no FSEL, no branch)
        asm("{\n\t"
            ".reg .pred q;\n\t"
            "setp.ge.f32 q, %1, %2;\n\t"
            "@q fma.rn.f32 %0, %3, %4, %0;\n\t"
            "}"
            : "+f"(acc)
            : "f"(tneg), "f"(lim), "f"(g), "f"(p.z));
    }

    if (n < N) atomicAdd(&out[b * N + n], acc);
}

extern "C" void kernel_launch(void* const* d_in, const int* in_sizes, int n_in,
                              void* d_out, int out_size) {
    const float* res_fields = (const float*)d_in[0];   // [B, M, 3]
    const float* width      = (const float*)d_in[1];   // [B, M]
    const float* A_mean     = (const float*)d_in[2];   // [B, M]
    const float* area       = (const float*)d_in[3];   // [M]
    const float* sf         = (const float*)d_in[4];   // [B, N]
    float* out = (float*)d_out;                        // [B, N]

    int M = in_sizes[3];
    int B = in_sizes[1] / M;
    int N = in_sizes[4] / B;

    int BN = B * N;
    int num_chunks = (M + CHUNK - 1) / CHUNK;

    zero_out_kernel<<<(BN + TPB - 1) / TPB, TPB>>>(out, BN);

    dim3 grid((N + TPB - 1) / TPB, num_chunks, B);
    spectra_main_kernel<<<grid, TPB>>>(res_fields, width, A_mean, area, sf, out, B, M, N);
}